// round 16
// baseline (speedup 1.0000x reference)
#include <cuda_runtime.h>
#include <cuda_fp16.h>
#include <cstdint>
#include <cstddef>

// Problem constants
#define BB   64
#define TT   12
#define HH   6400
#define G3   19200            // 3*H
#define IN0P 256              // layer-0 input size padded 200 -> 256
#define BH   (BB*HH)          // 409600
#define TBH  (TT*BB*HH)       // 4915200

// ---------------- device scratch (sanctioned: __device__ globals) -------------
__device__ __half g_Whh0[(size_t)G3*HH];
__device__ __half g_Wih1[(size_t)G3*HH];
__device__ __half g_Whh1[(size_t)G3*HH];
__device__ __half g_W0p [(size_t)G3*IN0P];
__device__ __half g_A0  [768*IN0P];
__device__ float  g_gi0 [(size_t)768*G3];
__device__ float  g_gi1 [(size_t)768*G3];
__device__ __half g_h0s [TBH];
__device__ float  g_gh  [(size_t)BB*G3];
__device__ float  g_h   [BH];
__device__ __half g_hh  [BH];

// ---------------- side stream + events (host objects, created pre-main) -------
struct SideStream {
    cudaStream_t s2;
    cudaEvent_t fork, w0, w1, w2;
    SideStream() {
        cudaStreamCreateWithFlags(&s2, cudaStreamNonBlocking);
        cudaEventCreateWithFlags(&fork, cudaEventDisableTiming);
        cudaEventCreateWithFlags(&w0,   cudaEventDisableTiming);
        cudaEventCreateWithFlags(&w1,   cudaEventDisableTiming);
        cudaEventCreateWithFlags(&w2,   cudaEventDisableTiming);
    }
};
static SideStream g_ss;

// ---------------- fp32 -> fp16 bulk convert -----------------------------------
__global__ void f2h_k(const float* __restrict__ s, __half* __restrict__ d, int n4)
{
    int i = blockIdx.x * blockDim.x + threadIdx.x;
    int str = gridDim.x * blockDim.x;
    for (; i < n4; i += str) {
        float4 v = ((const float4*)s)[i];
        __half2 h0 = __floats2half2_rn(v.x, v.y);
        __half2 h1 = __floats2half2_rn(v.z, v.w);
        uint2 o;
        o.x = *(uint32_t*)&h0;
        o.y = *(uint32_t*)&h1;
        ((uint2*)d)[i] = o;
    }
}

// layer-0 A: (B,T,200) -> padded (T*B, 256) fp16, row = t*64+b
__global__ void prep_a0_k(const float* __restrict__ x, __half* __restrict__ d)
{
    int idx = blockIdx.x * 256 + threadIdx.x;
    if (idx >= 768 * IN0P) return;
    int row = idx >> 8, c = idx & 255;
    int t = row >> 6, b = row & 63;
    float v = (c < 200) ? x[b * 2400 + t * 200 + c] : 0.f;
    d[idx] = __float2half_rn(v);
}

// W_ih0: (19200,200) -> padded (19200,256) fp16
__global__ void prep_w0_k(const float* __restrict__ w, __half* __restrict__ d)
{
    int idx = blockIdx.x * 256 + threadIdx.x;
    if (idx >= G3 * IN0P) return;
    int g = idx >> 8, c = idx & 255;
    float v = (c < 200) ? w[g * 200 + c] : 0.f;
    d[idx] = __float2half_rn(v);
}

// ---------------- pipelined fp16 tensor-core GEMM: C = A * W^T + bias ---------
// A: (M,K) fp16 rm, W: (N,K) fp16 rm, C: (M,N) fp32.
// CTA tile: (MT*64) x NTILE, 8 warps as 2(M) x 4(N). K-chunk = 64 halfs.
// NTILE=160 -> recurrence grid (1,120): EXACTLY one wave on 148 SMs (the old
// 150-CTA grid ran a 2-CTA second wave, doubling the step). NWT=5 (odd): the
// 5th n8-tile's W fragment comes from an x2 ldmatrix (lanes 0-15).
// S-stage cp.async pipeline, XOR-swizzled 128B rows, single-barrier mainloop.
__device__ __forceinline__ void cpa16(uint32_t d, const void* s)
{
    asm volatile("cp.async.cg.shared.global [%0], [%1], 16;\n" :: "r"(d), "l"(s));
}

template<int MT, int NTILE, int S, int MINB>
__global__ void __launch_bounds__(256, MINB) gemm_pipe(
    const __half* __restrict__ A, const __half* __restrict__ W,
    const float* __restrict__ bias, float* __restrict__ C,
    int N, int K)
{
    extern __shared__ char sm[];
    constexpr int AB  = MT * 64 * 128;    // A stage bytes
    constexpr int WB  = NTILE * 128;      // W stage bytes
    constexpr int SB  = AB + WB;          // stage stride
    constexpr int NWT = NTILE / 32;       // n8-tiles per warp

    const int tid  = threadIdx.x;
    const int warp = tid >> 5;
    const int lane = tid & 31;
    const int warpM = warp >> 2;          // 0..1
    const int warpN = warp & 3;           // 0..3
    const int mbase = blockIdx.x * (MT * 64);
    const int nbase = blockIdx.y * NTILE;
    const __half* Ab = A + (size_t)mbase * K;
    const __half* Wb = W + (size_t)nbase * K;
    const int nk = K >> 6;

    float acc[2 * MT][NWT][4];
#pragma unroll
    for (int a = 0; a < 2 * MT; a++)
#pragma unroll
        for (int b = 0; b < NWT; b++)
#pragma unroll
            for (int c = 0; c < 4; c++) acc[a][b][c] = 0.f;

    auto issue = [&](int slot, int it) {
        char* dA = sm + slot * SB;
        char* dW = dA + AB;
        const int kk = it << 6;
#pragma unroll
        for (int i = 0; i < NTILE / 32; i++) {        // W: NTILE rows x 8 chunks
            int cid = tid + 256 * i;
            int row = cid >> 3, c = cid & 7;
            cpa16((uint32_t)__cvta_generic_to_shared(
                      dW + row * 128 + ((c ^ (row & 7)) << 4)),
                  Wb + (size_t)row * K + kk + c * 8);
        }
#pragma unroll
        for (int i = 0; i < 2 * MT; i++) {            // A: MT*64 rows x 8 chunks
            int cid = tid + 256 * i;
            int row = cid >> 3, c = cid & 7;
            cpa16((uint32_t)__cvta_generic_to_shared(
                      dA + row * 128 + ((c ^ (row & 7)) << 4)),
                  Ab + (size_t)row * K + kk + c * 8);
        }
    };

    // prologue: issue stages 0..S-2, one commit group each
#pragma unroll
    for (int s = 0; s < S - 1; s++) {
        if (s < nk) issue(s, s);
        asm volatile("cp.async.commit_group;\n" ::);
    }
    asm volatile("cp.async.wait_group %0;\n" :: "n"(S - 2) : "memory");
    __syncthreads();

    for (int it = 0; it < nk; ++it) {
        const int rslot = it % S;
        const char* stA = sm + rslot * SB;
        const char* stW = stA + AB;

#pragma unroll
        for (int ks = 0; ks < 4; ks++) {
            // W fragments: warp's NTILE/4 N-cols = NWT n8-tiles
            uint32_t bw[NWT][2];
#pragma unroll
            for (int h = 0; h < NWT / 2; h++) {
                int row = warpN * (NTILE / 4) + h * 16 + (lane & 7) + ((lane >> 4) << 3);
                int c = 2 * ks + ((lane >> 3) & 1);
                uint32_t ad = (uint32_t)__cvta_generic_to_shared(
                    stW + row * 128 + ((c ^ (row & 7)) << 4));
                asm volatile(
                    "ldmatrix.sync.aligned.m8n8.x4.shared.b16 {%0,%1,%2,%3}, [%4];\n"
                    : "=r"(bw[2*h][0]), "=r"(bw[2*h][1]),
                      "=r"(bw[2*h+1][0]), "=r"(bw[2*h+1][1])
                    : "r"(ad));
            }
            if constexpr (NWT & 1) {
                // last n8-tile via x2 (matrices from lanes 0-15, mirroring the
                // x4 path's m0/m1 assignment: m0 = col chunk 2ks, m1 = 2ks+1)
                int row = warpN * (NTILE / 4) + (NWT - 1) * 8 + (lane & 7);
                int c = 2 * ks + ((lane >> 3) & 1);
                uint32_t ad = (uint32_t)__cvta_generic_to_shared(
                    stW + row * 128 + ((c ^ (row & 7)) << 4));
                asm volatile(
                    "ldmatrix.sync.aligned.m8n8.x2.shared.b16 {%0,%1}, [%2];\n"
                    : "=r"(bw[NWT-1][0]), "=r"(bw[NWT-1][1])
                    : "r"(ad));
            }
#pragma unroll
            for (int mtl = 0; mtl < 2 * MT; mtl++) {
                int row = (warpM * 2 * MT + mtl) * 16 + (lane & 15);
                int c = 2 * ks + (lane >> 4);
                uint32_t ad = (uint32_t)__cvta_generic_to_shared(
                    stA + row * 128 + ((c ^ (row & 7)) << 4));
                uint32_t a0, a1, a2, a3;
                asm volatile(
                    "ldmatrix.sync.aligned.m8n8.x4.shared.b16 {%0,%1,%2,%3}, [%4];\n"
                    : "=r"(a0), "=r"(a1), "=r"(a2), "=r"(a3) : "r"(ad));
#pragma unroll
                for (int nt = 0; nt < NWT; nt++) {
                    asm volatile(
                        "mma.sync.aligned.m16n8k16.row.col.f32.f16.f16.f32 "
                        "{%0,%1,%2,%3}, {%4,%5,%6,%7}, {%8,%9}, {%0,%1,%2,%3};\n"
                        : "+f"(acc[mtl][nt][0]), "+f"(acc[mtl][nt][1]),
                          "+f"(acc[mtl][nt][2]), "+f"(acc[mtl][nt][3])
                        : "r"(a0), "r"(a1), "r"(a2), "r"(a3),
                          "r"(bw[nt][0]), "r"(bw[nt][1]));
                }
            }
        }

        // issue stage it+S-1 into slot (it-1)%S, then single barrier.
        const int pre = it + S - 1;
        if (pre < nk) issue(pre % S, pre);
        asm volatile("cp.async.commit_group;\n" ::);
        asm volatile("cp.async.wait_group %0;\n" :: "n"(S - 2) : "memory");
        __syncthreads();
    }

    // epilogue: C[m][n] = acc + bias[n]
#pragma unroll
    for (int mtl = 0; mtl < 2 * MT; mtl++) {
        int row = mbase + (warpM * 2 * MT + mtl) * 16 + (lane >> 2);
#pragma unroll
        for (int nt = 0; nt < NWT; nt++) {
            int col = nbase + warpN * (NTILE / 4) + nt * 8 + (lane & 3) * 2;
            float bv0 = bias[col], bv1 = bias[col + 1];
            float2 v0 = make_float2(acc[mtl][nt][0] + bv0, acc[mtl][nt][1] + bv1);
            float2 v1 = make_float2(acc[mtl][nt][2] + bv0, acc[mtl][nt][3] + bv1);
            *(float2*)&C[(size_t)row * N + col]       = v0;
            *(float2*)&C[(size_t)(row + 8) * N + col] = v1;
        }
    }
}

// ---------------- fused GRU gate pointwise (float4 vectorized) -----------------
__global__ void gate_k(const float4* __restrict__ gi, const float4* __restrict__ gh,
                       const float4* __restrict__ hp, float4* __restrict__ ho,
                       uint2* __restrict__ hoh, float4* __restrict__ extra)
{
    int i = blockIdx.x * 256 + threadIdx.x;     // float4 index, 0..BH/4-1
    if (i >= BH / 4) return;
    int b = i / (HH / 4);
    int j = i - b * (HH / 4);
    const float4* gib = gi + (size_t)b * (G3 / 4);
    const float4* ghb = gh + (size_t)b * (G3 / 4);
    float4 gir = gib[j], giz = gib[j + HH/4], gin = gib[j + 2*(HH/4)];
    float4 ghr = ghb[j], ghz = ghb[j + HH/4], ghn = ghb[j + 2*(HH/4)];
    float4 h4  = hp[i];
    float4 o;
    {
        float r = 1.f / (1.f + __expf(-(gir.x + ghr.x)));
        float z = 1.f / (1.f + __expf(-(giz.x + ghz.x)));
        float n = tanhf(gin.x + r * ghn.x);
        o.x = fmaf(z, h4.x - n, n);
    }
    {
        float r = 1.f / (1.f + __expf(-(gir.y + ghr.y)));
        float z = 1.f / (1.f + __expf(-(giz.y + ghz.y)));
        float n = tanhf(gin.y + r * ghn.y);
        o.y = fmaf(z, h4.y - n, n);
    }
    {
        float r = 1.f / (1.f + __expf(-(gir.z + ghr.z)));
        float z = 1.f / (1.f + __expf(-(giz.z + ghz.z)));
        float n = tanhf(gin.z + r * ghn.z);
        o.z = fmaf(z, h4.z - n, n);
    }
    {
        float r = 1.f / (1.f + __expf(-(gir.w + ghr.w)));
        float z = 1.f / (1.f + __expf(-(giz.w + ghz.w)));
        float n = tanhf(gin.w + r * ghn.w);
        o.w = fmaf(z, h4.w - n, n);
    }
    ho[i] = o;
    __half2 lo = __floats2half2_rn(o.x, o.y);
    __half2 hi = __floats2half2_rn(o.z, o.w);
    uint2 u;
    u.x = *(uint32_t*)&lo;
    u.y = *(uint32_t*)&hi;
    hoh[i] = u;
    if (extra) extra[i] = o;
}

// ---- t=0 gate: h_prev = 0 so gh = b_hh exactly and h_new = (1-z)*n ------------
__global__ void gate0_k(const float4* __restrict__ gi, const float4* __restrict__ bhh,
                        float4* __restrict__ ho, uint2* __restrict__ hoh)
{
    int i = blockIdx.x * 256 + threadIdx.x;     // float4 index, 0..BH/4-1
    if (i >= BH / 4) return;
    int b = i / (HH / 4);
    int j = i - b * (HH / 4);
    const float4* gib = gi + (size_t)b * (G3 / 4);
    float4 gir = gib[j], giz = gib[j + HH/4], gin = gib[j + 2*(HH/4)];
    float4 br = bhh[j], bz = bhh[j + HH/4], bn = bhh[j + 2*(HH/4)];
    float4 o;
    {
        float r = 1.f / (1.f + __expf(-(gir.x + br.x)));
        float z = 1.f / (1.f + __expf(-(giz.x + bz.x)));
        float n = tanhf(gin.x + r * bn.x);
        o.x = fmaf(z, 0.f - n, n);
    }
    {
        float r = 1.f / (1.f + __expf(-(gir.y + br.y)));
        float z = 1.f / (1.f + __expf(-(giz.y + bz.y)));
        float n = tanhf(gin.y + r * bn.y);
        o.y = fmaf(z, 0.f - n, n);
    }
    {
        float r = 1.f / (1.f + __expf(-(gir.z + br.z)));
        float z = 1.f / (1.f + __expf(-(giz.z + bz.z)));
        float n = tanhf(gin.z + r * bn.z);
        o.z = fmaf(z, 0.f - n, n);
    }
    {
        float r = 1.f / (1.f + __expf(-(gir.w + br.w)));
        float z = 1.f / (1.f + __expf(-(giz.w + bz.w)));
        float n = tanhf(gin.w + r * bn.w);
        o.w = fmaf(z, 0.f - n, n);
    }
    ho[i] = o;
    __half2 lo = __floats2half2_rn(o.x, o.y);
    __half2 hi = __floats2half2_rn(o.z, o.w);
    uint2 u;
    u.x = *(uint32_t*)&lo;
    u.y = *(uint32_t*)&hi;
    hoh[i] = u;
}

// ---------------- host orchestration ------------------------------------------
extern "C" void kernel_launch(void* const* d_in, const int* in_sizes, int n_in,
                              void* d_out, int out_size)
{
    const float* x    = (const float*)d_in[0];
    const float* Wih0 = (const float*)d_in[1];
    const float* Whh0 = (const float*)d_in[2];
    const float* bih0 = (const float*)d_in[3];
    const float* bhh0 = (const float*)d_in[4];
    const float* Wih1 = (const float*)d_in[5];
    const float* Whh1 = (const float*)d_in[6];
    const float* bih1 = (const float*)d_in[7];
    const float* bhh1 = (const float*)d_in[8];
    float* out = (float*)d_out;

    __half *pWhh0, *pWih1, *pWhh1, *pW0p, *pA0, *pH0s, *pHh;
    float  *pGi0, *pGi1, *pGh, *pH;
    cudaGetSymbolAddress((void**)&pWhh0, g_Whh0);
    cudaGetSymbolAddress((void**)&pWih1, g_Wih1);
    cudaGetSymbolAddress((void**)&pWhh1, g_Whh1);
    cudaGetSymbolAddress((void**)&pW0p,  g_W0p);
    cudaGetSymbolAddress((void**)&pA0,   g_A0);
    cudaGetSymbolAddress((void**)&pH0s,  g_h0s);
    cudaGetSymbolAddress((void**)&pHh,   g_hh);
    cudaGetSymbolAddress((void**)&pGi0,  g_gi0);
    cudaGetSymbolAddress((void**)&pGi1,  g_gi1);
    cudaGetSymbolAddress((void**)&pGh,   g_gh);
    cudaGetSymbolAddress((void**)&pH,    g_h);

    // NTILE=160: recurrence grid (1,120) = single wave on 148 SMs.
    const int SMEM_BIG = 3 * (2 * 64 * 128 + 160 * 128);  // MT=2,NT=160,S=3 -> 108KB
    const int SMEM_REC = 6 * (64 * 128 + 160 * 128);      // MT=1,NT=160,S=6 -> 168KB
    cudaFuncSetAttribute(gemm_pipe<2,160,3,1>,
                         cudaFuncAttributeMaxDynamicSharedMemorySize, SMEM_BIG);
    cudaFuncSetAttribute(gemm_pipe<1,160,6,1>,
                         cudaFuncAttributeMaxDynamicSharedMemorySize, SMEM_REC);

    const int n4 = (G3 * HH) / 4;
    const int GATE_GRID = (BH / 4 + 255) / 256;   // 400
    const int NBLK = G3 / 160;                    // 120

    // fork side stream at time 0: all three weight conversions run there.
    // Whh0 is first needed at layer-0 t=1; Wih1 at gi1; Whh1 at layer-1 t=1.
    cudaEventRecord(g_ss.fork, 0);
    cudaStreamWaitEvent(g_ss.s2, g_ss.fork, 0);
    f2h_k<<<4096, 256, 0, g_ss.s2>>>(Whh0, pWhh0, n4);
    cudaEventRecord(g_ss.w0, g_ss.s2);
    f2h_k<<<4096, 256, 0, g_ss.s2>>>(Wih1, pWih1, n4);
    cudaEventRecord(g_ss.w1, g_ss.s2);
    f2h_k<<<4096, 256, 0, g_ss.s2>>>(Whh1, pWhh1, n4);
    cudaEventRecord(g_ss.w2, g_ss.s2);

    // main: layer-0 input projection (no conversion dependency)
    prep_a0_k<<<(768 * IN0P + 255) / 256, 256>>>(x, pA0);
    prep_w0_k<<<(G3 * IN0P + 255) / 256, 256>>>(Wih0, pW0p);
    gemm_pipe<2,160,3,1><<<dim3(6, NBLK), 256, SMEM_BIG>>>(
        pA0, pW0p, bih0, pGi0, G3, IN0P);

    // layer 0, t=0: h_prev = 0 -> gh = b_hh0 exactly, no GEMM needed
    gate0_k<<<GATE_GRID, 256>>>((const float4*)pGi0, (const float4*)bhh0,
                                (float4*)pH, (uint2*)pH0s);

    // layer 0 recurrence t=1..11 (needs converted Whh0)
    cudaStreamWaitEvent(0, g_ss.w0, 0);
    for (int t = 1; t < TT; t++) {
        const __half* Ah = pH0s + (size_t)(t - 1) * BH;
        gemm_pipe<1,160,6,1><<<dim3(1, NBLK), 256, SMEM_REC>>>(
            Ah, pWhh0, bhh0, pGh, G3, HH);
        float* extra = (t == TT - 1) ? (out + TBH) : nullptr;  // hidden[0]
        gate_k<<<GATE_GRID, 256>>>(
            (const float4*)(pGi0 + (size_t)t * 64 * G3), (const float4*)pGh,
            (const float4*)pH, (float4*)pH,
            (uint2*)(pH0s + (size_t)t * BH), (float4*)extra);
    }

    // gi1 = h0_states @ W_ih1^T + b_ih1   (768 x 19200, K=6400)
    cudaStreamWaitEvent(0, g_ss.w1, 0);
    gemm_pipe<2,160,3,1><<<dim3(6, NBLK), 256, SMEM_BIG>>>(
        pH0s, pWih1, bih1, pGi1, G3, HH);

    // layer 1, t=0: bias-only gate, writes directly to out[0]
    gate0_k<<<GATE_GRID, 256>>>((const float4*)pGi1, (const float4*)bhh1,
                                (float4*)out, (uint2*)pHh);

    // layer 1 recurrence t=1..11 (needs converted Whh1)
    cudaStreamWaitEvent(0, g_ss.w2, 0);
    for (int t = 1; t < TT; t++) {
        gemm_pipe<1,160,6,1><<<dim3(1, NBLK), 256, SMEM_REC>>>(
            pHh, pWhh1, bhh1, pGh, G3, HH);
        const float* hp = out + (size_t)(t - 1) * BH;
        float* extra = (t == TT - 1) ? (out + TBH + BH) : nullptr;  // hidden[1]
        gate_k<<<GATE_GRID, 256>>>(
            (const float4*)(pGi1 + (size_t)t * 64 * G3), (const float4*)pGh,
            (const float4*)hp, (float4*)(out + (size_t)t * BH),
            (uint2*)pHh, (float4*)extra);
    }
}

// round 17
// speedup vs baseline: 1.1207x; 1.1207x over previous
#include <cuda_runtime.h>
#include <cuda_fp16.h>
#include <cstdint>
#include <cstddef>

// Problem constants
#define BB   64
#define TT   12
#define HH   6400
#define G3   19200            // 3*H
#define IN0P 256              // layer-0 input size padded 200 -> 256
#define BH   (BB*HH)          // 409600
#define TBH  (TT*BB*HH)       // 4915200

// ---------------- device scratch (sanctioned: __device__ globals) -------------
__device__ __half g_Whh0[(size_t)G3*HH];
__device__ __half g_Wih1[(size_t)G3*HH];
__device__ __half g_Whh1[(size_t)G3*HH];
__device__ __half g_W0p [(size_t)G3*IN0P];
__device__ __half g_A0  [768*IN0P];
__device__ float  g_gi0 [(size_t)768*G3];
__device__ float  g_gi1 [(size_t)768*G3];
__device__ __half g_h0s [TBH];
__device__ float  g_gh  [(size_t)BB*G3];
__device__ float  g_h   [BH];
__device__ __half g_hh  [BH];

// ---------------- side stream + events (host objects, created pre-main) -------
struct SideStream {
    cudaStream_t s2;
    cudaEvent_t fork, w0, w1, w2;
    SideStream() {
        cudaStreamCreateWithFlags(&s2, cudaStreamNonBlocking);
        cudaEventCreateWithFlags(&fork, cudaEventDisableTiming);
        cudaEventCreateWithFlags(&w0,   cudaEventDisableTiming);
        cudaEventCreateWithFlags(&w1,   cudaEventDisableTiming);
        cudaEventCreateWithFlags(&w2,   cudaEventDisableTiming);
    }
};
static SideStream g_ss;

// ---------------- fp32 -> fp16 bulk convert -----------------------------------
__global__ void f2h_k(const float* __restrict__ s, __half* __restrict__ d, int n4)
{
    int i = blockIdx.x * blockDim.x + threadIdx.x;
    int str = gridDim.x * blockDim.x;
    for (; i < n4; i += str) {
        float4 v = ((const float4*)s)[i];
        __half2 h0 = __floats2half2_rn(v.x, v.y);
        __half2 h1 = __floats2half2_rn(v.z, v.w);
        uint2 o;
        o.x = *(uint32_t*)&h0;
        o.y = *(uint32_t*)&h1;
        ((uint2*)d)[i] = o;
    }
}

// layer-0 A: (B,T,200) -> padded (T*B, 256) fp16, row = t*64+b
__global__ void prep_a0_k(const float* __restrict__ x, __half* __restrict__ d)
{
    int idx = blockIdx.x * 256 + threadIdx.x;
    if (idx >= 768 * IN0P) return;
    int row = idx >> 8, c = idx & 255;
    int t = row >> 6, b = row & 63;
    float v = (c < 200) ? x[b * 2400 + t * 200 + c] : 0.f;
    d[idx] = __float2half_rn(v);
}

// W_ih0: (19200,200) -> padded (19200,256) fp16
__global__ void prep_w0_k(const float* __restrict__ w, __half* __restrict__ d)
{
    int idx = blockIdx.x * 256 + threadIdx.x;
    if (idx >= G3 * IN0P) return;
    int g = idx >> 8, c = idx & 255;
    float v = (c < 200) ? w[g * 200 + c] : 0.f;
    d[idx] = __float2half_rn(v);
}

// ---------------- pipelined fp16 tensor-core GEMM: C = A * W^T + bias ---------
// A: (M,K) fp16 rm, W: (N,K) fp16 rm, C: (M,N) fp32.
// CTA tile: (MT*64) x 128, 8 warps as 2(M) x 4(N). K-chunk = 64 halfs.
// S-stage cp.async pipeline, XOR-swizzled 128B rows, single-barrier mainloop.
// PDL: prologue issues ALL W prefetches first, then griddepsync, then A parts
// (group0 = all W + A0, groups 1..S-2 = A only; accounting matches original).
// Trigger fires before the epilogue so the dependent gate can start early.
__device__ __forceinline__ void cpa16(uint32_t d, const void* s)
{
    asm volatile("cp.async.cg.shared.global [%0], [%1], 16;\n" :: "r"(d), "l"(s));
}

template<int MT, int NTILE, int S, int MINB>
__global__ void __launch_bounds__(256, MINB) gemm_pipe(
    const __half* __restrict__ A, const __half* __restrict__ W,
    const float* __restrict__ bias, float* __restrict__ C,
    int N, int K)
{
    extern __shared__ char sm[];
    constexpr int AB  = MT * 64 * 128;    // A stage bytes
    constexpr int WB  = NTILE * 128;      // W stage bytes
    constexpr int SB  = AB + WB;          // stage stride
    constexpr int NWT = NTILE / 32;       // n8-tiles per warp

    const int tid  = threadIdx.x;
    const int warp = tid >> 5;
    const int lane = tid & 31;
    const int warpM = warp >> 2;          // 0..1
    const int warpN = warp & 3;           // 0..3
    const int mbase = blockIdx.x * (MT * 64);
    const int nbase = blockIdx.y * NTILE;
    const __half* Ab = A + (size_t)mbase * K;
    const __half* Wb = W + (size_t)nbase * K;
    const int nk = K >> 6;

    float acc[2 * MT][NWT][4];
#pragma unroll
    for (int a = 0; a < 2 * MT; a++)
#pragma unroll
        for (int b = 0; b < NWT; b++)
#pragma unroll
            for (int c = 0; c < 4; c++) acc[a][b][c] = 0.f;

    auto issueW = [&](int slot, int it) {
        char* dW = sm + slot * SB + AB;
        const int kk = it << 6;
#pragma unroll
        for (int i = 0; i < NTILE / 32; i++) {        // W: NTILE rows x 8 chunks
            int cid = tid + 256 * i;
            int row = cid >> 3, c = cid & 7;
            cpa16((uint32_t)__cvta_generic_to_shared(
                      dW + row * 128 + ((c ^ (row & 7)) << 4)),
                  Wb + (size_t)row * K + kk + c * 8);
        }
    };
    auto issueA = [&](int slot, int it) {
        char* dA = sm + slot * SB;
        const int kk = it << 6;
#pragma unroll
        for (int i = 0; i < 2 * MT; i++) {            // A: MT*64 rows x 8 chunks
            int cid = tid + 256 * i;
            int row = cid >> 3, c = cid & 7;
            cpa16((uint32_t)__cvta_generic_to_shared(
                      dA + row * 128 + ((c ^ (row & 7)) << 4)),
                  Ab + (size_t)row * K + kk + c * 8);
        }
    };

    // prologue: ALL W prefetches first (independent of previous kernel) ...
#pragma unroll
    for (int s = 0; s < S - 1; s++)
        if (s < nk) issueW(s, s);
    // ... wait for primary kernel (gate writing h = our A operand) ...
    cudaGridDependencySynchronize();
    // ... then A parts, one commit per stage (group0 swallows all W issues).
#pragma unroll
    for (int s = 0; s < S - 1; s++) {
        if (s < nk) issueA(s, s);
        asm volatile("cp.async.commit_group;\n" ::);
    }
    asm volatile("cp.async.wait_group %0;\n" :: "n"(S - 2) : "memory");
    __syncthreads();

    for (int it = 0; it < nk; ++it) {
        const int rslot = it % S;
        const char* stA = sm + rslot * SB;
        const char* stW = stA + AB;

#pragma unroll
        for (int ks = 0; ks < 4; ks++) {
            // W fragments: warp's NTILE/4 N-cols = NWT n8-tiles
            uint32_t bw[NWT][2];
#pragma unroll
            for (int h = 0; h < NWT / 2; h++) {
                int row = warpN * (NTILE / 4) + h * 16 + (lane & 7) + ((lane >> 4) << 3);
                int c = 2 * ks + ((lane >> 3) & 1);
                uint32_t ad = (uint32_t)__cvta_generic_to_shared(
                    stW + row * 128 + ((c ^ (row & 7)) << 4));
                asm volatile(
                    "ldmatrix.sync.aligned.m8n8.x4.shared.b16 {%0,%1,%2,%3}, [%4];\n"
                    : "=r"(bw[2*h][0]), "=r"(bw[2*h][1]),
                      "=r"(bw[2*h+1][0]), "=r"(bw[2*h+1][1])
                    : "r"(ad));
            }
#pragma unroll
            for (int mtl = 0; mtl < 2 * MT; mtl++) {
                int row = (warpM * 2 * MT + mtl) * 16 + (lane & 15);
                int c = 2 * ks + (lane >> 4);
                uint32_t ad = (uint32_t)__cvta_generic_to_shared(
                    stA + row * 128 + ((c ^ (row & 7)) << 4));
                uint32_t a0, a1, a2, a3;
                asm volatile(
                    "ldmatrix.sync.aligned.m8n8.x4.shared.b16 {%0,%1,%2,%3}, [%4];\n"
                    : "=r"(a0), "=r"(a1), "=r"(a2), "=r"(a3) : "r"(ad));
#pragma unroll
                for (int nt = 0; nt < NWT; nt++) {
                    asm volatile(
                        "mma.sync.aligned.m16n8k16.row.col.f32.f16.f16.f32 "
                        "{%0,%1,%2,%3}, {%4,%5,%6,%7}, {%8,%9}, {%0,%1,%2,%3};\n"
                        : "+f"(acc[mtl][nt][0]), "+f"(acc[mtl][nt][1]),
                          "+f"(acc[mtl][nt][2]), "+f"(acc[mtl][nt][3])
                        : "r"(a0), "r"(a1), "r"(a2), "r"(a3),
                          "r"(bw[nt][0]), "r"(bw[nt][1]));
                }
            }
        }

        // issue stage it+S-1 into slot (it-1)%S, then single barrier.
        const int pre = it + S - 1;
        if (pre < nk) { issueW(pre % S, pre); issueA(pre % S, pre); }
        asm volatile("cp.async.commit_group;\n" ::);
        asm volatile("cp.async.wait_group %0;\n" :: "n"(S - 2) : "memory");
        __syncthreads();
    }

    // allow dependent (gate) to launch and pre-load gi during our epilogue
    cudaTriggerProgrammaticLaunchCompletion();

    // epilogue: C[m][n] = acc + bias[n]
#pragma unroll
    for (int mtl = 0; mtl < 2 * MT; mtl++) {
        int row = mbase + (warpM * 2 * MT + mtl) * 16 + (lane >> 2);
#pragma unroll
        for (int nt = 0; nt < NWT; nt++) {
            int col = nbase + warpN * (NTILE / 4) + nt * 8 + (lane & 3) * 2;
            float bv0 = bias[col], bv1 = bias[col + 1];
            float2 v0 = make_float2(acc[mtl][nt][0] + bv0, acc[mtl][nt][1] + bv1);
            float2 v1 = make_float2(acc[mtl][nt][2] + bv0, acc[mtl][nt][3] + bv1);
            *(float2*)&C[(size_t)row * N + col]       = v0;
            *(float2*)&C[(size_t)(row + 8) * N + col] = v1;
        }
    }
}

// ---------------- fused GRU gate pointwise (float4 vectorized, PDL-aware) -----
// Loads gi (precomputed, safe pre-sync), then griddepsync, then gh/h_prev
// (written by the primary GEMM / transitively-ordered previous gate).
__global__ void gate_k(const float4* __restrict__ gi, const float4* __restrict__ gh,
                       const float4* __restrict__ hp, float4* __restrict__ ho,
                       uint2* __restrict__ hoh, float4* __restrict__ extra)
{
    // let the NEXT recurrence GEMM launch and prefetch its W immediately
    cudaTriggerProgrammaticLaunchCompletion();

    int i = blockIdx.x * 256 + threadIdx.x;     // float4 index, 0..BH/4-1
    if (i >= BH / 4) return;
    int b = i / (HH / 4);
    int j = i - b * (HH / 4);
    const float4* gib = gi + (size_t)b * (G3 / 4);
    float4 gir = gib[j], giz = gib[j + HH/4], gin = gib[j + 2*(HH/4)];

    // wait for primary (GEMM writing gh; transitively the prior gate for hp)
    cudaGridDependencySynchronize();

    const float4* ghb = gh + (size_t)b * (G3 / 4);
    float4 ghr = ghb[j], ghz = ghb[j + HH/4], ghn = ghb[j + 2*(HH/4)];
    float4 h4  = hp[i];
    float4 o;
    {
        float r = 1.f / (1.f + __expf(-(gir.x + ghr.x)));
        float z = 1.f / (1.f + __expf(-(giz.x + ghz.x)));
        float n = tanhf(gin.x + r * ghn.x);
        o.x = fmaf(z, h4.x - n, n);
    }
    {
        float r = 1.f / (1.f + __expf(-(gir.y + ghr.y)));
        float z = 1.f / (1.f + __expf(-(giz.y + ghz.y)));
        float n = tanhf(gin.y + r * ghn.y);
        o.y = fmaf(z, h4.y - n, n);
    }
    {
        float r = 1.f / (1.f + __expf(-(gir.z + ghr.z)));
        float z = 1.f / (1.f + __expf(-(giz.z + ghz.z)));
        float n = tanhf(gin.z + r * ghn.z);
        o.z = fmaf(z, h4.z - n, n);
    }
    {
        float r = 1.f / (1.f + __expf(-(gir.w + ghr.w)));
        float z = 1.f / (1.f + __expf(-(giz.w + ghz.w)));
        float n = tanhf(gin.w + r * ghn.w);
        o.w = fmaf(z, h4.w - n, n);
    }
    ho[i] = o;
    __half2 lo = __floats2half2_rn(o.x, o.y);
    __half2 hi = __floats2half2_rn(o.z, o.w);
    uint2 u;
    u.x = *(uint32_t*)&lo;
    u.y = *(uint32_t*)&hi;
    hoh[i] = u;
    if (extra) extra[i] = o;
}

// ---- t=0 gate: h_prev = 0 so gh = b_hh exactly and h_new = (1-z)*n ------------
__global__ void gate0_k(const float4* __restrict__ gi, const float4* __restrict__ bhh,
                        float4* __restrict__ ho, uint2* __restrict__ hoh)
{
    int i = blockIdx.x * 256 + threadIdx.x;     // float4 index, 0..BH/4-1
    if (i >= BH / 4) return;
    int b = i / (HH / 4);
    int j = i - b * (HH / 4);
    const float4* gib = gi + (size_t)b * (G3 / 4);
    float4 gir = gib[j], giz = gib[j + HH/4], gin = gib[j + 2*(HH/4)];
    float4 br = bhh[j], bz = bhh[j + HH/4], bn = bhh[j + 2*(HH/4)];
    float4 o;
    {
        float r = 1.f / (1.f + __expf(-(gir.x + br.x)));
        float z = 1.f / (1.f + __expf(-(giz.x + bz.x)));
        float n = tanhf(gin.x + r * bn.x);
        o.x = fmaf(z, 0.f - n, n);
    }
    {
        float r = 1.f / (1.f + __expf(-(gir.y + br.y)));
        float z = 1.f / (1.f + __expf(-(giz.y + bz.y)));
        float n = tanhf(gin.y + r * bn.y);
        o.y = fmaf(z, 0.f - n, n);
    }
    {
        float r = 1.f / (1.f + __expf(-(gir.z + br.z)));
        float z = 1.f / (1.f + __expf(-(giz.z + bz.z)));
        float n = tanhf(gin.z + r * bn.z);
        o.z = fmaf(z, 0.f - n, n);
    }
    {
        float r = 1.f / (1.f + __expf(-(gir.w + br.w)));
        float z = 1.f / (1.f + __expf(-(giz.w + bz.w)));
        float n = tanhf(gin.w + r * bn.w);
        o.w = fmaf(z, 0.f - n, n);
    }
    ho[i] = o;
    __half2 lo = __floats2half2_rn(o.x, o.y);
    __half2 hi = __floats2half2_rn(o.z, o.w);
    uint2 u;
    u.x = *(uint32_t*)&lo;
    u.y = *(uint32_t*)&hi;
    hoh[i] = u;
}

// ---------------- host orchestration ------------------------------------------
extern "C" void kernel_launch(void* const* d_in, const int* in_sizes, int n_in,
                              void* d_out, int out_size)
{
    const float* x    = (const float*)d_in[0];
    const float* Wih0 = (const float*)d_in[1];
    const float* Whh0 = (const float*)d_in[2];
    const float* bih0 = (const float*)d_in[3];
    const float* bhh0 = (const float*)d_in[4];
    const float* Wih1 = (const float*)d_in[5];
    const float* Whh1 = (const float*)d_in[6];
    const float* bih1 = (const float*)d_in[7];
    const float* bhh1 = (const float*)d_in[8];
    float* out = (float*)d_out;

    __half *pWhh0, *pWih1, *pWhh1, *pW0p, *pA0, *pH0s, *pHh;
    float  *pGi0, *pGi1, *pGh, *pH;
    cudaGetSymbolAddress((void**)&pWhh0, g_Whh0);
    cudaGetSymbolAddress((void**)&pWih1, g_Wih1);
    cudaGetSymbolAddress((void**)&pWhh1, g_Whh1);
    cudaGetSymbolAddress((void**)&pW0p,  g_W0p);
    cudaGetSymbolAddress((void**)&pA0,   g_A0);
    cudaGetSymbolAddress((void**)&pH0s,  g_h0s);
    cudaGetSymbolAddress((void**)&pHh,   g_hh);
    cudaGetSymbolAddress((void**)&pGi0,  g_gi0);
    cudaGetSymbolAddress((void**)&pGi1,  g_gi1);
    cudaGetSymbolAddress((void**)&pGh,   g_gh);
    cudaGetSymbolAddress((void**)&pH,    g_h);

    // R15-exact tile configs (proven best): MT=2/S=3 big, MT=1/S=6 recurrence
    const int SMEM_BIG = 3 * (2 * 64 * 128 + 128 * 128);  // 96KB
    const int SMEM_REC = 6 * (64 * 128 + 128 * 128);      // 144KB
    cudaFuncSetAttribute(gemm_pipe<2,128,3,2>,
                         cudaFuncAttributeMaxDynamicSharedMemorySize, SMEM_BIG);
    cudaFuncSetAttribute(gemm_pipe<1,128,6,2>,
                         cudaFuncAttributeMaxDynamicSharedMemorySize, SMEM_REC);

    const int n4 = (G3 * HH) / 4;
    const int GATE_GRID = (BH / 4 + 255) / 256;   // 400

    // PDL launch configs
    cudaLaunchAttribute pdlAttr[1];
    pdlAttr[0].id = cudaLaunchAttributeProgrammaticStreamSerialization;
    pdlAttr[0].val.programmaticStreamSerializationAllowed = 1;

    cudaLaunchConfig_t cfgRec = {};
    cfgRec.gridDim = dim3(1, G3 / 128);
    cfgRec.blockDim = dim3(256);
    cfgRec.dynamicSmemBytes = SMEM_REC;
    cfgRec.stream = 0;
    cfgRec.attrs = pdlAttr;
    cfgRec.numAttrs = 1;

    cudaLaunchConfig_t cfgGate = {};
    cfgGate.gridDim = dim3(GATE_GRID);
    cfgGate.blockDim = dim3(256);
    cfgGate.dynamicSmemBytes = 0;
    cfgGate.stream = 0;
    cfgGate.attrs = pdlAttr;
    cfgGate.numAttrs = 1;

    // fork side stream at time 0: all three weight conversions run there.
    cudaEventRecord(g_ss.fork, 0);
    cudaStreamWaitEvent(g_ss.s2, g_ss.fork, 0);
    f2h_k<<<4096, 256, 0, g_ss.s2>>>(Whh0, pWhh0, n4);
    cudaEventRecord(g_ss.w0, g_ss.s2);
    f2h_k<<<4096, 256, 0, g_ss.s2>>>(Wih1, pWih1, n4);
    cudaEventRecord(g_ss.w1, g_ss.s2);
    f2h_k<<<4096, 256, 0, g_ss.s2>>>(Whh1, pWhh1, n4);
    cudaEventRecord(g_ss.w2, g_ss.s2);

    // main: layer-0 input projection (no conversion dependency)
    prep_a0_k<<<(768 * IN0P + 255) / 256, 256>>>(x, pA0);
    prep_w0_k<<<(G3 * IN0P + 255) / 256, 256>>>(Wih0, pW0p);
    gemm_pipe<2,128,3,2><<<dim3(6, G3 / 128), 256, SMEM_BIG>>>(
        pA0, pW0p, bih0, pGi0, G3, IN0P);

    // layer 0, t=0: h_prev = 0 -> gh = b_hh0 exactly, no GEMM needed
    gate0_k<<<GATE_GRID, 256>>>((const float4*)pGi0, (const float4*)bhh0,
                                (float4*)pH, (uint2*)pH0s);

    // layer 0 recurrence t=1..11
    cudaStreamWaitEvent(0, g_ss.w0, 0);
    for (int t = 1; t < TT; t++) {
        const __half* Ah = pH0s + (size_t)(t - 1) * BH;
        if (t == 1) {   // preceded by event wait: plain launch
            gemm_pipe<1,128,6,2><<<dim3(1, G3 / 128), 256, SMEM_REC>>>(
                Ah, pWhh0, bhh0, pGh, G3, HH);
        } else {        // preceded by gate_k: PDL overlap
            cudaLaunchKernelEx(&cfgRec, gemm_pipe<1,128,6,2>,
                               Ah, (const __half*)pWhh0, bhh0, pGh,
                               (int)G3, (int)HH);
        }
        float* extra = (t == TT - 1) ? (out + TBH) : nullptr;  // hidden[0]
        cudaLaunchKernelEx(&cfgGate, gate_k,
                           (const float4*)(pGi0 + (size_t)t * 64 * G3),
                           (const float4*)pGh, (const float4*)pH,
                           (float4*)pH, (uint2*)(pH0s + (size_t)t * BH),
                           (float4*)extra);
    }

    // gi1 = h0_states @ W_ih1^T + b_ih1   (768 x 19200, K=6400)
    cudaStreamWaitEvent(0, g_ss.w1, 0);
    gemm_pipe<2,128,3,2><<<dim3(6, G3 / 128), 256, SMEM_BIG>>>(
        pH0s, pWih1, bih1, pGi1, G3, HH);

    // layer 1, t=0: bias-only gate, writes directly to out[0]
    gate0_k<<<GATE_GRID, 256>>>((const float4*)pGi1, (const float4*)bhh1,
                                (float4*)out, (uint2*)pHh);

    // layer 1 recurrence t=1..11
    cudaStreamWaitEvent(0, g_ss.w2, 0);
    for (int t = 1; t < TT; t++) {
        if (t == 1) {   // preceded by event wait: plain launch
            gemm_pipe<1,128,6,2><<<dim3(1, G3 / 128), 256, SMEM_REC>>>(
                pHh, pWhh1, bhh1, pGh, G3, HH);
        } else {        // preceded by gate_k: PDL overlap
            cudaLaunchKernelEx(&cfgRec, gemm_pipe<1,128,6,2>,
                               (const __half*)pHh, (const __half*)pWhh1,
                               bhh1, pGh, (int)G3, (int)HH);
        }
        const float* hp = out + (size_t)(t - 1) * BH;
        float* extra = (t == TT - 1) ? (out + TBH + BH) : nullptr;  // hidden[1]
        cudaLaunchKernelEx(&cfgGate, gate_k,
                           (const float4*)(pGi1 + (size_t)t * 64 * G3),
                           (const float4*)pGh, (const float4*)hp,
                           (float4*)(out + (size_t)t * BH),
                           (uint2*)pHh, (float4*)extra);
    }
}